// round 17
// baseline (speedup 1.0000x reference)
#include <cuda_runtime.h>
#include <cuda_bf16.h>
#include <stdint.h>
#include <math.h>

#define BB 2
#define TT 2048
#define CC 1024
#define HH 16
#define DHD 64
#define MTOT (BB*TT)

// ---- GEMM smem: 3 stages x 4 arrays x 128 rows x 64B (XOR-swizzled) ----
#define GAR_N 8192             // 128 * 64 B
#define GSTG_N (4 * GAR_N)     // 32768 B per stage
#define GSMEM_N (3 * GSTG_N)   // 98304 B

// ---- Attention smem: 3-stage KV ring; Q staged transiently in stage 1 ----
#define AROW_B 144
#define QAR (128 * AROW_B)     // 18432 (per Q array; Qh+Ql = one 36,864B stage)
#define KAR (64 * AROW_B)      // 9216
#define KVSTG (4 * KAR)        // 36864 per stage: kh | kl | vh | vl
#define ASMEM (3 * KVSTG)      // 110592

// ---- scratch (no allocation allowed) ----
__device__ __nv_bfloat16 g_xh[MTOT * CC], g_xl[MTOT * CC];
__device__ __nv_bfloat16 g_wch[3 * CC * CC], g_wcl[3 * CC * CC];   // wq|wk|wv
__device__ __nv_bfloat16 g_woh[CC * CC], g_wol[CC * CC];
__device__ __nv_bfloat16 g_qkvh[MTOT * 3 * CC], g_qkvl[MTOT * 3 * CC];
__device__ __nv_bfloat16 g_ph[MTOT * CC], g_pl[MTOT * CC];
__device__ float g_bias3[3 * CC];
__device__ float g_mask[MTOT];

__device__ __forceinline__ uint32_t smem_u32(const void* p) {
    return (uint32_t)__cvta_generic_to_shared(p);
}

#define LDSM_X4(r0, r1, r2, r3, addr)                                          \
    asm volatile("ldmatrix.sync.aligned.m8n8.x4.shared.b16 {%0,%1,%2,%3}, [%4];" \
                 : "=r"(r0), "=r"(r1), "=r"(r2), "=r"(r3) : "r"(addr))
#define LDSM_X4_T(r0, r1, r2, r3, addr)                                        \
    asm volatile("ldmatrix.sync.aligned.m8n8.x4.trans.shared.b16 {%0,%1,%2,%3}, [%4];" \
                 : "=r"(r0), "=r"(r1), "=r"(r2), "=r"(r3) : "r"(addr))

#define MMA_BF16(d, a, b)                                                      \
    asm volatile("mma.sync.aligned.m16n8k16.row.col.f32.bf16.bf16.f32 "        \
                 "{%0,%1,%2,%3}, {%4,%5,%6,%7}, {%8,%9}, {%0,%1,%2,%3};"       \
                 : "+f"((d)[0]), "+f"((d)[1]), "+f"((d)[2]), "+f"((d)[3])      \
                 : "r"((a)[0]), "r"((a)[1]), "r"((a)[2]), "r"((a)[3]),         \
                   "r"((b)[0]), "r"((b)[1]))

#define CP_ASYNC16(saddr, gaddr)                                               \
    asm volatile("cp.async.cg.shared.global [%0], [%1], 16;"                   \
                 :: "r"(saddr), "l"(gaddr))
#define CP_COMMIT  asm volatile("cp.async.commit_group;")
#define CP_WAIT0   asm volatile("cp.async.wait_group 0;")
#define CP_WAIT1   asm volatile("cp.async.wait_group 1;")

// split fp32 pair -> packed bf16 hi + packed bf16 residual
__device__ __forceinline__ void split2(float a, float b, uint32_t& hi, uint32_t& lo) {
    __nv_bfloat162 h = __float22bfloat162_rn(make_float2(a, b));
    float2 hf = __bfloat1622float2(h);
    __nv_bfloat162 l = __float22bfloat162_rn(make_float2(a - hf.x, b - hf.y));
    hi = *reinterpret_cast<uint32_t*>(&h);
    lo = *reinterpret_cast<uint32_t*>(&l);
}

// ---------------------------------------------------------------------------
// fused preamble (unchanged, passing)
// ---------------------------------------------------------------------------
#define N4X (MTOT * CC / 4)
#define N4W (CC * CC / 4)
__global__ void split_all(const float* __restrict__ x,
                          const float* __restrict__ wq, const float* __restrict__ wk,
                          const float* __restrict__ wv, const float* __restrict__ wo,
                          const float* __restrict__ bq, const float* __restrict__ bk,
                          const float* __restrict__ bv,
                          __nv_bfloat16* __restrict__ xh, __nv_bfloat16* __restrict__ xl,
                          __nv_bfloat16* __restrict__ wch, __nv_bfloat16* __restrict__ wcl,
                          __nv_bfloat16* __restrict__ woh, __nv_bfloat16* __restrict__ wol,
                          float* __restrict__ bias3, float* __restrict__ mask) {
    int i = blockIdx.x * blockDim.x + threadIdx.x;
    const float* in;
    __nv_bfloat16 *oh, *ol;
    int jr, jw;
    if (i < N4X) {
        in = x; oh = xh; ol = xl; jr = i; jw = i;
    } else {
        int t = i - N4X;
        int w = t >> 18;
        jr = t & (N4W - 1);
        if (w == 0)      { in = wq; oh = wch; ol = wcl; jw = jr; }
        else if (w == 1) { in = wk; oh = wch; ol = wcl; jw = jr + N4W; }
        else if (w == 2) { in = wv; oh = wch; ol = wcl; jw = jr + 2 * N4W; }
        else             { in = wo; oh = woh; ol = wol; jw = jr; }
    }
    float4 v = ((const float4*)in)[jr];
    uint32_t h01, l01, h23, l23;
    split2(v.x, v.y, h01, l01);
    split2(v.z, v.w, h23, l23);
    ((uint32_t*)oh)[jw * 2] = h01;
    ((uint32_t*)oh)[jw * 2 + 1] = h23;
    ((uint32_t*)ol)[jw * 2] = l01;
    ((uint32_t*)ol)[jw * 2 + 1] = l23;
    if (i < MTOT) mask[i] = (x[(size_t)i * CC] != 0.0f) ? 0.f : -INFINITY;
    if (i < 3 * CC)
        bias3[i] = (i < CC) ? bq[i] : (i < 2 * CC) ? bk[i - CC] : bv[i - 2 * CC];
}

// ---------------------------------------------------------------------------
// bf16-input NT GEMM, 3-term compensated, 3-stage cp.async, ONE sync/iter.
// (reverted to R15 passing version — legacy mma.sync path)
// ---------------------------------------------------------------------------
__global__ __launch_bounds__(256, 2) void gemm_bf16_tc(
    const __nv_bfloat16* __restrict__ Ah, const __nv_bfloat16* __restrict__ Al,
    const __nv_bfloat16* __restrict__ Bh, const __nv_bfloat16* __restrict__ Bl,
    const float* __restrict__ bias, float* __restrict__ outf,
    __nv_bfloat16* __restrict__ outh, __nv_bfloat16* __restrict__ outl,
    int M, int N, int K, int out_split) {
    extern __shared__ char sgc[];
    const uint32_t sbase = smem_u32(sgc);
    const int tid = threadIdx.x;
    const int wid = tid >> 5, lane = tid & 31;
    const int warp_m = wid >> 2, warp_n = wid & 3;
    const int m0 = blockIdx.y * 128, n0 = blockIdx.x * 128;

    float acc[4][4][4];
#pragma unroll
    for (int mt = 0; mt < 4; mt++)
#pragma unroll
        for (int nt = 0; nt < 4; nt++)
#pragma unroll
            for (int e = 0; e < 4; e++) acc[mt][nt][e] = 0.f;

    uint32_t a_off[4][2], b_off[2][2];
#pragma unroll
    for (int mt = 0; mt < 4; mt++)
#pragma unroll
        for (int ks = 0; ks < 2; ks++) {
            int row = warp_m * 64 + mt * 16 + (lane & 15);
            int c = ks * 2 + (lane >> 4);
            a_off[mt][ks] = (uint32_t)(row * 64 + ((c ^ ((row >> 1) & 3)) << 4));
        }
#pragma unroll
    for (int p = 0; p < 2; p++)
#pragma unroll
        for (int ks = 0; ks < 2; ks++) {
            int row = warp_n * 32 + (2 * p + (lane >> 4)) * 8 + (lane & 7);
            int c = ks * 2 + ((lane >> 3) & 1);
            b_off[p][ks] = (uint32_t)(row * 64 + ((c ^ ((row >> 1) & 3)) << 4));
        }

    auto issue = [&](int k0, int s) {
#pragma unroll
        for (int t = 0; t < 8; t++) {
            int idx = tid + t * 256;
            int a = idx >> 9, loc = idx & 511;
            int r = loc >> 2, cc = loc & 3;
            const __nv_bfloat16* gp = (a == 0) ? Ah : (a == 1) ? Al
                                     : (a == 2) ? Bh : Bl;
            int row = ((a < 2) ? m0 : n0) + r;
            CP_ASYNC16(sbase + s * GSTG_N + a * GAR_N + r * 64 +
                           ((cc ^ ((r >> 1) & 3)) << 4),
                       gp + (size_t)row * K + k0 + cc * 8);
        }
        CP_COMMIT;
    };

    const int NIT = K / 32;
    issue(0, 0);
    issue(32, 1);
    for (int it = 0; it < NIT; it++) {
        if (it + 1 < NIT) { CP_WAIT1; } else { CP_WAIT0; }
        __syncthreads();
        if (it + 2 < NIT) issue((it + 2) * 32, (it + 2) % 3);

        const uint32_t stg = sbase + (it % 3) * GSTG_N;
#pragma unroll
        for (int term = 0; term < 3; term++) {
            uint32_t abase = stg + ((term == 2) ? GAR_N : 0);
            uint32_t bbase = stg + 2 * GAR_N + ((term == 1) ? GAR_N : 0);
#pragma unroll
            for (int ks = 0; ks < 2; ks++) {
                uint32_t af[4][4], bf[4][2];
#pragma unroll
                for (int mt = 0; mt < 4; mt++)
                    LDSM_X4(af[mt][0], af[mt][1], af[mt][2], af[mt][3],
                            abase + a_off[mt][ks]);
#pragma unroll
                for (int p = 0; p < 2; p++)
                    LDSM_X4(bf[2 * p][0], bf[2 * p][1], bf[2 * p + 1][0],
                            bf[2 * p + 1][1], bbase + b_off[p][ks]);
#pragma unroll
                for (int mt = 0; mt < 4; mt++)
#pragma unroll
                    for (int nt = 0; nt < 4; nt++)
                        MMA_BF16(acc[mt][nt], af[mt], bf[nt]);
            }
        }
    }

    const int g = lane >> 2, c = lane & 3;
#pragma unroll
    for (int nt = 0; nt < 4; nt++) {
        int col = n0 + warp_n * 32 + nt * 8 + c * 2;
        float b0 = bias[col], b1 = bias[col + 1];
#pragma unroll
        for (int mt = 0; mt < 4; mt++) {
            int row = m0 + warp_m * 64 + mt * 16 + g;
            float v00 = acc[mt][nt][0] + b0, v01 = acc[mt][nt][1] + b1;
            float v10 = acc[mt][nt][2] + b0, v11 = acc[mt][nt][3] + b1;
            if (out_split) {
                uint32_t hi, lo;
                split2(v00, v01, hi, lo);
                *(uint32_t*)&outh[(size_t)row * N + col] = hi;
                *(uint32_t*)&outl[(size_t)row * N + col] = lo;
                split2(v10, v11, hi, lo);
                *(uint32_t*)&outh[(size_t)(row + 8) * N + col] = hi;
                *(uint32_t*)&outl[(size_t)(row + 8) * N + col] = lo;
            } else {
                *(float2*)&outf[(size_t)row * N + col] = make_float2(v00, v01);
                *(float2*)&outf[(size_t)(row + 8) * N + col] = make_float2(v10, v11);
            }
        }
    }
}

// ---------------------------------------------------------------------------
// Tensor-core flash attention: 3-stage KV ring, ONE sync per key tile.
// Q staged transiently in ring stage 1; both Q hi/lo fragments persistent
// in registers. P-split moved inside the ks loop (8 live regs, not 32).
// ---------------------------------------------------------------------------
__global__ __launch_bounds__(256, 2) void attn_tc(
    const __nv_bfloat16* __restrict__ qh, const __nv_bfloat16* __restrict__ ql,
    const __nv_bfloat16* __restrict__ kh, const __nv_bfloat16* __restrict__ kl,
    const __nv_bfloat16* __restrict__ vh, const __nv_bfloat16* __restrict__ vl,
    const float* __restrict__ mask,
    __nv_bfloat16* __restrict__ ph, __nv_bfloat16* __restrict__ pl, int qs) {
    extern __shared__ char sac[];
    const uint32_t sbase = smem_u32(sac);

    const int tid = threadIdx.x;
    const int w = tid >> 5, lane = tid & 31;
    const int g = lane >> 2, qc = lane & 3;
    const int bh = blockIdx.y;
    const int b = bh / HH, h = bh % HH;
    const int q0 = blockIdx.x * 128;

    auto issue_kv = [&](int kt, int s) {
#pragma unroll
        for (int t = 0; t < 8; t++) {
            int idx = tid + t * 256;
            int a = idx >> 9, loc = idx & 511;
            int r = loc >> 3, cc = loc & 7;
            const __nv_bfloat16* gp = (a == 0) ? kh : (a == 1) ? kl
                                     : (a == 2) ? vh : vl;
            CP_ASYNC16(sbase + s * KVSTG + a * KAR + r * AROW_B + cc * 16,
                       gp + (size_t)(b * TT + kt * 64 + r) * qs + h * DHD + cc * 8);
        }
        CP_COMMIT;
    };

    // ---- preamble: Q (hi|lo) into ring stage 1; KV tile 0 into stage 0 ----
    {
#pragma unroll
        for (int t = 0; t < 8; t++) {
            int idx = tid + t * 256;
            int a = idx >> 10, loc = idx & 1023;
            int r = loc >> 3, cc = loc & 7;
            const __nv_bfloat16* gp = a ? ql : qh;
            CP_ASYNC16(sbase + KVSTG + a * QAR + r * AROW_B + cc * 16,
                       gp + (size_t)(b * TT + q0 + r) * qs + h * DHD + cc * 8);
        }
        CP_COMMIT;
    }
    issue_kv(0, 0);
    CP_WAIT0;
    __syncthreads();

    // ---- extract Q hi AND lo fragments (persistent in registers) ----
    const uint32_t qaoff = (uint32_t)((w * 16 + (lane & 15)) * AROW_B +
                                      ((lane >> 4) << 4));
    uint32_t qf_h[4][4], qf_l[4][4];
#pragma unroll
    for (int ks = 0; ks < 4; ks++) {
        LDSM_X4(qf_h[ks][0], qf_h[ks][1], qf_h[ks][2], qf_h[ks][3],
                sbase + KVSTG + qaoff + ks * 32);
        LDSM_X4(qf_l[ks][0], qf_l[ks][1], qf_l[ks][2], qf_l[ks][3],
                sbase + KVSTG + QAR + qaoff + ks * 32);
    }
    __syncthreads();          // all warps done reading Q region
    issue_kv(1, 1);           // overwrites stage 1 (Q) — safe now

    const uint32_t hilo = (lane >> 4) ? KAR : 0;
    const uint32_t k_lane = hilo + (uint32_t)((lane & 7) * AROW_B +
                                              (((lane >> 3) & 1) << 4));
    const uint32_t v_lane = hilo + (uint32_t)((lane & 15) * AROW_B);

    float oacc[8][4];
#pragma unroll
    for (int jd = 0; jd < 8; jd++)
#pragma unroll
        for (int e = 0; e < 4; e++) oacc[jd][e] = 0.f;
    float m0i = -INFINITY, m1i = -INFINITY, l0i = 0.f, l1i = 0.f;

    const int NT = TT / 64;
    for (int kt = 0; kt < NT; kt++) {
        if (kt + 1 < NT) { CP_WAIT1; } else { CP_WAIT0; }
        __syncthreads();
        if (kt + 2 < NT) issue_kv(kt + 2, (kt + 2) % 3);

        const uint32_t kh_b = sbase + (kt % 3) * KVSTG;   // + KAR = kl
        const uint32_t vh_b = kh_b + 2 * KAR;             // + KAR = vl

        // ---- S = Q K^T (3-term compensated) ----
        float sacc[8][4];
#pragma unroll
        for (int j = 0; j < 8; j++)
#pragma unroll
            for (int e = 0; e < 4; e++) sacc[j][e] = 0.f;

#pragma unroll
        for (int ks = 0; ks < 4; ks++) {
#pragma unroll
            for (int j = 0; j < 8; j++) {
                uint32_t bh2[2], bl2[2];
                LDSM_X4(bh2[0], bh2[1], bl2[0], bl2[1],
                        kh_b + k_lane + (uint32_t)(j * 8 * AROW_B) + ks * 32);
                MMA_BF16(sacc[j], qf_h[ks], bh2);
                MMA_BF16(sacc[j], qf_h[ks], bl2);
                MMA_BF16(sacc[j], qf_l[ks], bh2);
            }
        }

        // ---- scale + mask ----
        const float* mrow = &mask[b * TT + kt * 64];
#pragma unroll
        for (int j = 0; j < 8; j++) {
            float km0 = mrow[j * 8 + 2 * qc];
            float km1 = mrow[j * 8 + 2 * qc + 1];
            sacc[j][0] = sacc[j][0] * 0.125f + km0;
            sacc[j][1] = sacc[j][1] * 0.125f + km1;
            sacc[j][2] = sacc[j][2] * 0.125f + km0;
            sacc[j][3] = sacc[j][3] * 0.125f + km1;
        }

        // ---- online softmax ----
        float mx0 = -INFINITY, mx1 = -INFINITY;
#pragma unroll
        for (int j = 0; j < 8; j++) {
            mx0 = fmaxf(mx0, fmaxf(sacc[j][0], sacc[j][1]));
            mx1 = fmaxf(mx1, fmaxf(sacc[j][2], sacc[j][3]));
        }
        mx0 = fmaxf(mx0, __shfl_xor_sync(0xffffffffu, mx0, 1));
        mx0 = fmaxf(mx0, __shfl_xor_sync(0xffffffffu, mx0, 2));
        mx1 = fmaxf(mx1, __shfl_xor_sync(0xffffffffu, mx1, 1));
        mx1 = fmaxf(mx1, __shfl_xor_sync(0xffffffffu, mx1, 2));
        float mn0 = fmaxf(m0i, mx0), mn1 = fmaxf(m1i, mx1);
        float esc0 = __expf(m0i - mn0), esc1 = __expf(m1i - mn1);
        float rs0 = 0.f, rs1 = 0.f;
#pragma unroll
        for (int j = 0; j < 8; j++) {
            float p0 = __expf(sacc[j][0] - mn0);
            float p1 = __expf(sacc[j][1] - mn0);
            float p2 = __expf(sacc[j][2] - mn1);
            float p3 = __expf(sacc[j][3] - mn1);
            sacc[j][0] = p0; sacc[j][1] = p1; sacc[j][2] = p2; sacc[j][3] = p3;
            rs0 += p0 + p1;
            rs1 += p2 + p3;
        }
        rs0 += __shfl_xor_sync(0xffffffffu, rs0, 1);
        rs0 += __shfl_xor_sync(0xffffffffu, rs0, 2);
        rs1 += __shfl_xor_sync(0xffffffffu, rs1, 1);
        rs1 += __shfl_xor_sync(0xffffffffu, rs1, 2);
        l0i = l0i * esc0 + rs0;
        l1i = l1i * esc1 + rs1;
        m0i = mn0; m1i = mn1;
#pragma unroll
        for (int jd = 0; jd < 8; jd++) {
            oacc[jd][0] *= esc0; oacc[jd][1] *= esc0;
            oacc[jd][2] *= esc1; oacc[jd][3] *= esc1;
        }

        // ---- O += P V (3-term); P split per-ks (8 live regs) ----
#pragma unroll
        for (int ks = 0; ks < 4; ks++) {
            uint32_t pf_h[4], pf_l[4];
            int j0 = 2 * ks, j1 = 2 * ks + 1;
            split2(sacc[j0][0], sacc[j0][1], pf_h[0], pf_l[0]);
            split2(sacc[j0][2], sacc[j0][3], pf_h[1], pf_l[1]);
            split2(sacc[j1][0], sacc[j1][1], pf_h[2], pf_l[2]);
            split2(sacc[j1][2], sacc[j1][3], pf_h[3], pf_l[3]);
#pragma unroll
            for (int jd = 0; jd < 8; jd++) {
                uint32_t bvh[2], bvl[2];
                LDSM_X4_T(bvh[0], bvh[1], bvl[0], bvl[1],
                          vh_b + v_lane + (uint32_t)(ks * 16 * AROW_B) + jd * 16);
                MMA_BF16(oacc[jd], pf_h, bvh);
                MMA_BF16(oacc[jd], pf_h, bvl);
                MMA_BF16(oacc[jd], pf_l, bvh);
            }
        }
        // no bottom sync: ring stage reuse is protected by next iter's top sync
    }

    // ---- epilogue: normalize + split-store ----
    float inv0 = 1.f / l0i, inv1 = 1.f / l1i;
    const int r0 = q0 + w * 16 + g;
    const size_t obase = (size_t)(b * TT + r0) * CC + h * DHD;
#pragma unroll
    for (int jd = 0; jd < 8; jd++) {
        int col = jd * 8 + 2 * qc;
        uint32_t hi, lo;
        split2(oacc[jd][0] * inv0, oacc[jd][1] * inv0, hi, lo);
        *(uint32_t*)&ph[obase + col] = hi;
        *(uint32_t*)&pl[obase + col] = lo;
        split2(oacc[jd][2] * inv1, oacc[jd][3] * inv1, hi, lo);
        *(uint32_t*)&ph[obase + 8 * CC + col] = hi;
        *(uint32_t*)&pl[obase + 8 * CC + col] = lo;
    }
}

// ---------------------------------------------------------------------------
extern "C" void kernel_launch(void* const* d_in, const int* in_sizes, int n_in,
                              void* d_out, int out_size) {
    const float* x   = (const float*)d_in[0];
    const float* wq  = (const float*)d_in[1];
    const float* bq  = (const float*)d_in[2];
    const float* wk  = (const float*)d_in[3];
    const float* bk  = (const float*)d_in[4];
    const float* wv  = (const float*)d_in[5];
    const float* bv  = (const float*)d_in[6];
    const float* wo  = (const float*)d_in[7];
    const float* bo  = (const float*)d_in[8];
    float* out = (float*)d_out;

    __nv_bfloat16 *xh, *xl, *wch, *wcl, *woh, *wol, *qkvh, *qkvl, *ph, *pl;
    float *bias3, *maskp;
    cudaGetSymbolAddress((void**)&xh, g_xh);     cudaGetSymbolAddress((void**)&xl, g_xl);
    cudaGetSymbolAddress((void**)&wch, g_wch);   cudaGetSymbolAddress((void**)&wcl, g_wcl);
    cudaGetSymbolAddress((void**)&woh, g_woh);   cudaGetSymbolAddress((void**)&wol, g_wol);
    cudaGetSymbolAddress((void**)&qkvh, g_qkvh); cudaGetSymbolAddress((void**)&qkvl, g_qkvl);
    cudaGetSymbolAddress((void**)&ph, g_ph);     cudaGetSymbolAddress((void**)&pl, g_pl);
    cudaGetSymbolAddress((void**)&bias3, g_bias3);
    cudaGetSymbolAddress((void**)&maskp, g_mask);

    cudaFuncSetAttribute(gemm_bf16_tc, cudaFuncAttributeMaxDynamicSharedMemorySize,
                         GSMEM_N);
    cudaFuncSetAttribute(attn_tc, cudaFuncAttributeMaxDynamicSharedMemorySize,
                         ASMEM);

    split_all<<<(N4X + 4 * N4W + 255) / 256, 256>>>(
        x, wq, wk, wv, wo, bq, bk, bv, xh, xl, wch, wcl, woh, wol, bias3, maskp);

    // fused QKV: [4096,1024] x [3072,1024]^T -> split bf16 [4096,3072]
    gemm_bf16_tc<<<dim3(3 * CC / 128, MTOT / 128), 256, GSMEM_N>>>(
        xh, xl, wch, wcl, bias3, nullptr, qkvh, qkvl, MTOT, 3 * CC, CC, 1);

    attn_tc<<<dim3(TT / 128, BB * HH), 256, ASMEM>>>(
        qkvh, qkvl, qkvh + CC, qkvl + CC, qkvh + 2 * CC, qkvl + 2 * CC,
        maskp, ph, pl, 3 * CC);

    gemm_bf16_tc<<<dim3(CC / 128, MTOT / 128), 256, GSMEM_N>>>(
        ph, pl, woh, wol, bo, out, nullptr, nullptr, MTOT, CC, CC, 0);
}